// round 8
// baseline (speedup 1.0000x reference)
#include <cuda_runtime.h>

#define NVOX    150000
#define CIN     32
#define COUT    64
#define KCENTER 13
#define NBLK    296
#define TILE_M  128
#define NTILES  ((NVOX + TILE_M - 1) / TILE_M)   // 1172
#define FPITCH  130                              // F-tile row pitch (conflict-tuned)
#define SOPITCH 68                               // out-tile row pitch (conflict-tuned)
#define MAXE    512

__device__ float    g_stats[2*COUT];   // zero at load; reset by last block each run
__device__ unsigned g_bar, g_done;

// ---------------------------------------------------------------- f32x2 helpers
__device__ __forceinline__ unsigned long long dup2(float x) {
    unsigned long long r; asm("mov.b64 %0, {%1, %1};" : "=l"(r) : "f"(x)); return r;
}
__device__ __forceinline__ unsigned long long pack2(float x, float y) {
    unsigned long long r; asm("mov.b64 %0, {%1, %2};" : "=l"(r) : "f"(x), "f"(y)); return r;
}
__device__ __forceinline__ void unpack2(unsigned long long v, float& x, float& y) {
    asm("mov.b64 {%0, %1}, %2;" : "=f"(x), "=f"(y) : "l"(v));
}
__device__ __forceinline__ void ffma2(unsigned long long& acc,
                                      unsigned long long a, unsigned long long b) {
    asm("fma.rn.f32x2 %0, %1, %2, %0;" : "+l"(acc) : "l"(a), "l"(b));
}
__device__ __forceinline__ unsigned long long add2(unsigned long long a, unsigned long long b) {
    unsigned long long r; asm("add.rn.f32x2 %0, %1, %2;" : "=l"(r) : "l"(a), "l"(b)); return r;
}

// smem carve (floats):
//  sFt   [0,           4160)   CIN*FPITCH
//  sW    [4160,        6208)   CIN*COUT
//  sOut  [6208,       14912)   TILE_M*SOPITCH
//  sList [14912,      15936)   MAXE int2
//  sRed  [15936,      18016)   512 float4 + pad (16B aligned: 15936*4=63744 ok)
//  sCnt  [18016]
//  sc/sh [18020, 18148)
#define OFF_FT   0
#define OFF_W    (CIN*FPITCH)                    // 4160
#define OFF_OUT  (OFF_W + CIN*COUT)              // 6208
#define OFF_LIST (OFF_OUT + TILE_M*SOPITCH)      // 14912
#define OFF_RED  (OFF_LIST + 2*MAXE)             // 15936
#define OFF_CNT  (OFF_RED + 4*512)               // 17984
#define OFF_SC   (OFF_CNT + 4)
#define SMEM_FLOATS (OFF_SC + 2*COUT + 4)
#define SMEM_BYTES  (SMEM_FLOATS*4)

extern "C" __global__ __launch_bounds__(256, 2)
void fused_kernel(const float* __restrict__ features,
                  const float* __restrict__ weight,
                  const float* __restrict__ gamma,
                  const float* __restrict__ beta,
                  const int*   __restrict__ nbr,
                  float* __restrict__ out)
{
    extern __shared__ float dsm[];
    float*  sFt   = dsm + OFF_FT;
    float*  sW    = dsm + OFF_W;
    float*  sOut  = dsm + OFF_OUT;
    int2*   sList = (int2*)(dsm + OFF_LIST);
    float4* sRed  = (float4*)(dsm + OFF_RED);
    int*    sCnt  = (int*)(dsm + OFF_CNT);
    float*  sc    = dsm + OFF_SC;
    float*  sh    = sc + COUT;

    const int t    = threadIdx.x;
    const int lane = t & 31;
    const int warp = t >> 5;
    const int tm   = t & 15;           // row group
    const int tn   = t >> 4;           // channel group
    const int d0   = tn * 4;           // dense channels
    const int d0e  = lane * 2;         // extras channels

    // stage center weights once
    for (int e = t; e < CIN*COUT; e += 256)
        sW[e] = weight[KCENTER*CIN*COUT + e];

    float4 s4 = make_float4(0,0,0,0), q4 = make_float4(0,0,0,0);

    for (int tile = blockIdx.x; tile < NTILES; tile += NBLK) {
        const int n0 = tile * TILE_M;
        __syncthreads();   // prev tile's smem reads done; sW ready on first iter

        // zero out-tile
        #pragma unroll 4
        for (int e = t; e < TILE_M*SOPITCH/4; e += 256)
            ((float4*)sOut)[e] = make_float4(0,0,0,0);

        // stage F transposed: sFt[c][r]
        #pragma unroll
        for (int e = t; e < TILE_M*8; e += 256) {
            int r = e >> 3, c4 = (e & 7) * 4;
            float4 v = make_float4(0,0,0,0);
            if (n0 + r < NVOX)
                v = ((const float4*)features)[(size_t)(n0 + r)*8 + (e & 7)];
            sFt[(c4+0)*FPITCH + r] = v.x;
            sFt[(c4+1)*FPITCH + r] = v.y;
            sFt[(c4+2)*FPITCH + r] = v.z;
            sFt[(c4+3)*FPITCH + r] = v.w;
        }

        if (t == 0) *sCnt = 0;
        __syncthreads();

        // build extras list (26 offsets x 128 rows, coalesced; 13 full-warp iters)
        for (int e = t; e < 26*TILE_M; e += 256) {
            int j = e >> 7, r = e & (TILE_M-1);
            int k = j + (j >= KCENTER);
            int n = n0 + r;
            int idx = (n < NVOX) ? __ldg(&nbr[(size_t)k*NVOX + n]) : -1;
            bool valid = idx >= 0;
            unsigned msk = __ballot_sync(0xffffffffu, valid);
            if (msk) {
                int ldr = __ffs(msk) - 1;
                int base = 0;
                if (lane == ldr) base = atomicAdd(sCnt, __popc(msk));
                base = __shfl_sync(0xffffffffu, base, ldr);
                if (valid)
                    sList[base + __popc(msk & ((1u << lane) - 1))] =
                        make_int2((k << 16) | r, idx);
            }
        }
        __syncthreads();   // sFt, sOut=0, list ready

        // extras: warp per entry, accumulate into sOut
        const int cnt = *sCnt;
        for (int e = warp; e < cnt; e += 8) {
            int2 ent = sList[e];
            int r = ent.x & 0xffff, k = ent.x >> 16, idx = ent.y;
            const float4* f4 = (const float4*)(features + (size_t)idx*CIN);
            const float* wk = weight + k*CIN*COUT + d0e;
            unsigned long long aA = 0ull, aB = 0ull;
            #pragma unroll
            for (int jj = 0; jj < 8; jj++) {
                float4 v = f4[jj];                               // broadcast
                float2 w0 = __ldg((const float2*)(wk + (4*jj+0)*COUT));
                float2 w1 = __ldg((const float2*)(wk + (4*jj+1)*COUT));
                float2 w2 = __ldg((const float2*)(wk + (4*jj+2)*COUT));
                float2 w3 = __ldg((const float2*)(wk + (4*jj+3)*COUT));
                ffma2(aA, dup2(v.x), pack2(w0.x, w0.y));
                ffma2(aB, dup2(v.y), pack2(w1.x, w1.y));
                ffma2(aA, dup2(v.z), pack2(w2.x, w2.y));
                ffma2(aB, dup2(v.w), pack2(w3.x, w3.y));
            }
            float x0, x1; unpack2(add2(aA, aB), x0, x1);
            atomicAdd(&sOut[r*SOPITCH + d0e],     x0);
            atomicAdd(&sOut[r*SOPITCH + d0e + 1], x1);
        }
        __syncthreads();   // sOut complete

        // dense 128x64x32 GEMM: thread = 8 rows (4 pairs) x 4 channels
        unsigned long long A[4][4];
        #pragma unroll
        for (int p = 0; p < 4; p++)
            #pragma unroll
            for (int j = 0; j < 4; j++) A[p][j] = 0ull;

        #pragma unroll
        for (int c = 0; c < CIN; c++) {
            const float* frow = &sFt[c*FPITCH + 2*tm];
            unsigned long long f0 = *(const unsigned long long*)(frow);
            unsigned long long f1 = *(const unsigned long long*)(frow + 32);
            unsigned long long f2 = *(const unsigned long long*)(frow + 64);
            unsigned long long f3 = *(const unsigned long long*)(frow + 96);
            float4 w4 = *(const float4*)&sW[c*COUT + d0];
            unsigned long long wd0 = dup2(w4.x), wd1 = dup2(w4.y),
                               wd2 = dup2(w4.z), wd3 = dup2(w4.w);
            ffma2(A[0][0], f0, wd0); ffma2(A[0][1], f0, wd1);
            ffma2(A[0][2], f0, wd2); ffma2(A[0][3], f0, wd3);
            ffma2(A[1][0], f1, wd0); ffma2(A[1][1], f1, wd1);
            ffma2(A[1][2], f1, wd2); ffma2(A[1][3], f1, wd3);
            ffma2(A[2][0], f2, wd0); ffma2(A[2][1], f2, wd1);
            ffma2(A[2][2], f2, wd2); ffma2(A[2][3], f2, wd3);
            ffma2(A[3][0], f3, wd0); ffma2(A[3][1], f3, wd1);
            ffma2(A[3][2], f3, wd2); ffma2(A[3][3], f3, wd3);
        }

        // merge extras, accumulate stats, store
        #pragma unroll
        for (int p = 0; p < 4; p++) {
            int r0 = 2*tm + 32*p;
            float v0[4], v1[4];
            #pragma unroll
            for (int j = 0; j < 4; j++) unpack2(A[p][j], v0[j], v1[j]);
            float4 e0 = *(const float4*)&sOut[(r0  )*SOPITCH + d0];
            float4 e1 = *(const float4*)&sOut[(r0+1)*SOPITCH + d0];
            v0[0]+=e0.x; v0[1]+=e0.y; v0[2]+=e0.z; v0[3]+=e0.w;
            v1[0]+=e1.x; v1[1]+=e1.y; v1[2]+=e1.z; v1[3]+=e1.w;

            s4.x += v0[0]+v1[0]; s4.y += v0[1]+v1[1];
            s4.z += v0[2]+v1[2]; s4.w += v0[3]+v1[3];
            q4.x = fmaf(v0[0],v0[0], fmaf(v1[0],v1[0], q4.x));
            q4.y = fmaf(v0[1],v0[1], fmaf(v1[1],v1[1], q4.y));
            q4.z = fmaf(v0[2],v0[2], fmaf(v1[2],v1[2], q4.z));
            q4.w = fmaf(v0[3],v0[3], fmaf(v1[3],v1[3], q4.w));

            if (n0 + r0 < NVOX)
                *(float4*)(out + (size_t)(n0+r0)*COUT + d0) =
                    make_float4(v0[0], v0[1], v0[2], v0[3]);
            if (n0 + r0 + 1 < NVOX)
                *(float4*)(out + (size_t)(n0+r0+1)*COUT + d0) =
                    make_float4(v1[0], v1[1], v1[2], v1[3]);
        }
    }

    // ---------------- block stats reduce -> global atomics --------------------
    __syncthreads();
    sRed[t]       = s4;
    sRed[256 + t] = q4;
    __syncthreads();
    if (t < 16) {
        float4 S = make_float4(0,0,0,0), Q = make_float4(0,0,0,0);
        #pragma unroll
        for (int i = 0; i < 16; i++) {
            float4 a = sRed[t*16 + i];
            float4 b = sRed[256 + t*16 + i];
            S.x += a.x; S.y += a.y; S.z += a.z; S.w += a.w;
            Q.x += b.x; Q.y += b.y; Q.z += b.z; Q.w += b.w;
        }
        atomicAdd(&g_stats[4*t+0], S.x); atomicAdd(&g_stats[4*t+1], S.y);
        atomicAdd(&g_stats[4*t+2], S.z); atomicAdd(&g_stats[4*t+3], S.w);
        atomicAdd(&g_stats[COUT+4*t+0], Q.x); atomicAdd(&g_stats[COUT+4*t+1], Q.y);
        atomicAdd(&g_stats[COUT+4*t+2], Q.z); atomicAdd(&g_stats[COUT+4*t+3], Q.w);
    }

    // ---------------- grid barrier (all 296 blocks resident) ------------------
    __threadfence();
    __syncthreads();
    if (t == 0) {
        atomicAdd(&g_bar, 1u);
        while (*(volatile unsigned*)&g_bar < (unsigned)gridDim.x) __nanosleep(64);
    }
    __syncthreads();
    __threadfence();

    // ---------------- finalize + normalize (out is L2-hot) --------------------
    if (t < COUT) {
        float inv_n = 1.0f / (float)NVOX;
        float mean  = g_stats[t] * inv_n;
        float var   = g_stats[COUT + t] * inv_n - mean*mean;
        float inv   = rsqrtf(var + 1e-5f);
        float scl   = gamma[t] * inv;
        sc[t] = scl;
        sh[t] = beta[t] - mean*scl;
    }
    __syncthreads();

    const int total4 = NVOX*COUT/4;
    float4* o4 = (float4*)out;
    for (int i = blockIdx.x*256 + t; i < total4; i += NBLK*256) {
        float4 v = o4[i];
        int bd = (i*4) & (COUT-1);
        v.x = fmaxf(fmaf(v.x, sc[bd+0], sh[bd+0]), 0.f);
        v.y = fmaxf(fmaf(v.y, sc[bd+1], sh[bd+1]), 0.f);
        v.z = fmaxf(fmaf(v.z, sc[bd+2], sh[bd+2]), 0.f);
        v.w = fmaxf(fmaf(v.w, sc[bd+3], sh[bd+3]), 0.f);
        o4[i] = v;
    }

    // ---------------- reset globals for next graph replay ---------------------
    __syncthreads();
    if (t == 0) {
        unsigned d = atomicAdd(&g_done, 1u);
        if (d == (unsigned)gridDim.x - 1u) {
            #pragma unroll
            for (int i = 0; i < 2*COUT; i++) g_stats[i] = 0.f;
            __threadfence();
            g_bar  = 0u;
            g_done = 0u;
            __threadfence();
        }
    }
}

// ---------------------------------------------------------------- launch
extern "C" void kernel_launch(void* const* d_in, const int* in_sizes, int n_in,
                              void* d_out, int out_size)
{
    const float* features = (const float*)d_in[0];  // [150000,32]
    const float* weight   = (const float*)d_in[1];  // [27,32,64]
    const float* gamma    = (const float*)d_in[2];  // [64]
    const float* beta     = (const float*)d_in[3];  // [64]
    const int*   nbr      = (const int*)  d_in[4];  // [27,150000]
    float* out = (float*)d_out;                     // [150000,64]

    cudaFuncSetAttribute(fused_kernel,
                         cudaFuncAttributeMaxDynamicSharedMemorySize, SMEM_BYTES);
    fused_kernel<<<NBLK, 256, SMEM_BYTES>>>(features, weight, gamma, beta, nbr, out);
}

// round 9
// speedup vs baseline: 1.0951x; 1.0951x over previous
#include <cuda_runtime.h>
#include <cstdint>

#define NVOX    150000
#define CIN     32
#define COUT    64
#define KCENTER 13
#define NBLK    296
#define NWARPS  8
#define NCHUNK  ((NVOX + 31) / 32)    // 4688
#define MAXE    128
#define FULLM   0xffffffffu

__device__ float    g_stats[2*COUT];
__device__ unsigned g_work, g_bar1, g_bar2, g_done;

// ---------------------------------------------------------------- f32x2 helpers
__device__ __forceinline__ unsigned long long dup2(float x) {
    unsigned long long r; asm("mov.b64 %0, {%1, %1};" : "=l"(r) : "f"(x)); return r;
}
__device__ __forceinline__ unsigned long long pack2(float x, float y) {
    unsigned long long r; asm("mov.b64 %0, {%1, %2};" : "=l"(r) : "f"(x), "f"(y)); return r;
}
__device__ __forceinline__ void unpack2(unsigned long long v, float& x, float& y) {
    asm("mov.b64 {%0, %1}, %2;" : "=f"(x), "=f"(y) : "l"(v));
}
__device__ __forceinline__ void ffma2(unsigned long long& acc,
                                      unsigned long long a, unsigned long long b) {
    asm("fma.rn.f32x2 %0, %1, %2, %0;" : "+l"(acc) : "l"(a), "l"(b));
}
__device__ __forceinline__ unsigned long long add2(unsigned long long a, unsigned long long b) {
    unsigned long long r; asm("add.rn.f32x2 %0, %1, %2;" : "=l"(r) : "l"(a), "l"(b)); return r;
}

// ---------------------------------------------------------------- cp.async
__device__ __forceinline__ uint32_t s2u(const void* p) {
    return (uint32_t)__cvta_generic_to_shared(p);
}
__device__ __forceinline__ void cp16(uint32_t d, const void* s) {
    asm volatile("cp.async.cg.shared.global [%0], [%1], 16;" :: "r"(d), "l"(s));
}
__device__ __forceinline__ void cp4(uint32_t d, const void* s) {
    asm volatile("cp.async.ca.shared.global [%0], [%1], 4;" :: "r"(d), "l"(s));
}
__device__ __forceinline__ void cpwait() {
    asm volatile("cp.async.commit_group;\ncp.async.wait_group 0;" ::: "memory");
}

// smem carve (bytes):
//  sF    [0,      32768)  NWARPS * 32 rows * 8 float4
//  sIdx  [32768,  59392)  NWARPS * 26*32 int
//  sList [59392,  67584)  NWARPS * MAXE int2
//  sRed  [67584,  75776)  512 float4
//  sc/sh [75776,  76288)
#define SMEM_BYTES 76288

extern "C" __global__ void __launch_bounds__(256, 2)
fused_kernel(const float* __restrict__ features,
             const float* __restrict__ weight,
             const float* __restrict__ gamma,
             const float* __restrict__ beta,
             const int*   __restrict__ nbr,
             float* __restrict__ out)
{
    extern __shared__ unsigned char dsm[];
    float4* sF    = (float4*)dsm;
    int*    sIdxA = (int*)(dsm + 32768);
    int2*   sLstA = (int2*)(dsm + 59392);
    float4* sRed  = (float4*)(dsm + 67584);
    float*  sc    = (float*)(dsm + 75776);
    float*  sh    = sc + COUT;

    const int t    = threadIdx.x;
    const int lane = t & 31;
    const int warp = t >> 5;
    const int d0   = lane * 2;

    float4* sFw   = sF    + warp * 256;
    int*    sIdxW = sIdxA + warp * 26*32;
    int2*   sLstW = sLstA + warp * MAXE;

    // center weights in registers: W13[c][d0:d0+2]
    unsigned long long w[CIN];
    {
        const float* wc = weight + KCENTER*CIN*COUT + d0;
        #pragma unroll
        for (int c = 0; c < CIN; c++) {
            float2 v = __ldg((const float2*)(wc + c*COUT));
            w[c] = pack2(v.x, v.y);
        }
    }

    // ---------------- phase 1: conv (work-stealing chunks) -------------------
    for (;;) {
        int chunk;
        if (lane == 0) chunk = (int)atomicAdd(&g_work, 1u);
        chunk = __shfl_sync(FULLM, chunk, 0);
        if (chunk >= NCHUNK) break;

        const int n0 = chunk * 32;
        const int nv = min(32, NVOX - n0);

        // stage 32 feature rows: 8 cp.async.16B per lane
        {
            const float4* src = (const float4*)(features + (size_t)n0 * CIN);
            uint32_t dst = s2u(sFw);
            #pragma unroll
            for (int j = 0; j < 8; j++) {
                int e = j*32 + lane;
                if ((e >> 3) < nv) cp16(dst + e*16, src + e);
            }
        }
        // stage 26 nbr indices per lane: cp.async.4B
        {
            const int nl = n0 + lane;
            uint32_t dst = s2u(sIdxW);
            if (nl < NVOX) {
                #pragma unroll
                for (int j = 0; j < 26; j++) {
                    int k = j + (j >= KCENTER);
                    cp4(dst + (j*32 + lane)*4, nbr + (size_t)k*NVOX + nl);
                }
            } else {
                #pragma unroll
                for (int j = 0; j < 26; j++) sIdxW[j*32 + lane] = -1;
            }
        }
        cpwait();
        __syncwarp();

        // build compacted extras list (k, row, idx)
        int cnt = 0;
        #pragma unroll
        for (int j = 0; j < 26; j++) {
            int idx = sIdxW[j*32 + lane];
            unsigned msk = __ballot_sync(FULLM, idx >= 0);
            if (idx >= 0) {
                int k = j + (j >= KCENTER);
                int pos = cnt + __popc(msk & ((1u << lane) - 1u));
                if (pos < MAXE) sLstW[pos] = make_int2((k << 8) | lane, idx);
            }
            cnt += __popc(msk);
        }
        if (cnt > MAXE) cnt = MAXE;
        __syncwarp();

        // dense center GEMM: 2 voxels per iteration, 4 independent chains
        for (int i = 0; i < nv; i += 2) {
            const float4* fr = sFw + i*8;
            unsigned long long aA=0ull, aB=0ull, bA=0ull, bB=0ull;
            #pragma unroll
            for (int j = 0; j < 8; j++) {
                float4 u = fr[j];
                float4 v = fr[8 + j];
                ffma2(aA, dup2(u.x), w[4*j+0]);
                ffma2(aB, dup2(u.y), w[4*j+1]);
                ffma2(aA, dup2(u.z), w[4*j+2]);
                ffma2(aB, dup2(u.w), w[4*j+3]);
                ffma2(bA, dup2(v.x), w[4*j+0]);
                ffma2(bB, dup2(v.y), w[4*j+1]);
                ffma2(bA, dup2(v.z), w[4*j+2]);
                ffma2(bB, dup2(v.w), w[4*j+3]);
            }
            float a0, a1, b0, b1;
            unpack2(add2(aA, aB), a0, a1);
            unpack2(add2(bA, bB), b0, b1);
            *(float2*)(out + (size_t)(n0+i  )*COUT + d0) = make_float2(a0, a1);
            *(float2*)(out + (size_t)(n0+i+1)*COUT + d0) = make_float2(b0, b1);
        }

        // extras: idx already known -> single DRAM exposure per entry
        for (int e = 0; e < cnt; e++) {
            int2 ent = sLstW[e];                       // LDS.64 broadcast
            int k = ent.x >> 8, i = ent.x & 255, idx = ent.y;
            const float4* f4 = (const float4*)(features + (size_t)idx * CIN);
            const float*  wk = weight + k*CIN*COUT + d0;
            unsigned long long aA = 0ull, aB = 0ull;
            #pragma unroll
            for (int jj = 0; jj < 8; jj++) {
                float4 v  = f4[jj];
                float2 w0 = __ldg((const float2*)(wk + (4*jj+0)*COUT));
                float2 w1 = __ldg((const float2*)(wk + (4*jj+1)*COUT));
                float2 w2 = __ldg((const float2*)(wk + (4*jj+2)*COUT));
                float2 w3 = __ldg((const float2*)(wk + (4*jj+3)*COUT));
                ffma2(aA, dup2(v.x), pack2(w0.x, w0.y));
                ffma2(aB, dup2(v.y), pack2(w1.x, w1.y));
                ffma2(aA, dup2(v.z), pack2(w2.x, w2.y));
                ffma2(aB, dup2(v.w), pack2(w3.x, w3.y));
            }
            float x0, x1; unpack2(add2(aA, aB), x0, x1);
            asm volatile("red.global.add.v2.f32 [%0], {%1, %2};"
                         :: "l"(out + (size_t)(n0+i)*COUT + d0), "f"(x0), "f"(x1)
                         : "memory");
        }
    }

    // ---------------- barrier 1 ------------------------------------------------
    __threadfence();
    __syncthreads();
    if (t == 0) {
        atomicAdd(&g_bar1, 1u);
        while (*(volatile unsigned*)&g_bar1 < (unsigned)NBLK) __nanosleep(64);
    }
    __syncthreads();
    __threadfence();

    // ---------------- phase 2a: stats over out (L2-hot) -----------------------
    {
        float4 s = make_float4(0,0,0,0), q = make_float4(0,0,0,0);
        const float4* o4 = (const float4*)out;
        const int total4 = NVOX*COUT/4;
        for (int i = blockIdx.x*256 + t; i < total4; i += NBLK*256) {
            float4 v = o4[i];
            s.x += v.x; s.y += v.y; s.z += v.z; s.w += v.w;
            q.x = fmaf(v.x, v.x, q.x); q.y = fmaf(v.y, v.y, q.y);
            q.z = fmaf(v.z, v.z, q.z); q.w = fmaf(v.w, v.w, q.w);
        }
        int grp = t & 15, mem = t >> 4;            // thread's fixed channel group
        sRed[grp*16 + mem]       = s;
        sRed[256 + grp*16 + mem] = q;
        __syncthreads();
        if (t < 16) {
            float4 S = make_float4(0,0,0,0), Q = make_float4(0,0,0,0);
            #pragma unroll
            for (int i = 0; i < 16; i++) {
                float4 a = sRed[t*16 + i];
                float4 b = sRed[256 + t*16 + i];
                S.x += a.x; S.y += a.y; S.z += a.z; S.w += a.w;
                Q.x += b.x; Q.y += b.y; Q.z += b.z; Q.w += b.w;
            }
            atomicAdd(&g_stats[4*t+0], S.x); atomicAdd(&g_stats[4*t+1], S.y);
            atomicAdd(&g_stats[4*t+2], S.z); atomicAdd(&g_stats[4*t+3], S.w);
            atomicAdd(&g_stats[COUT+4*t+0], Q.x); atomicAdd(&g_stats[COUT+4*t+1], Q.y);
            atomicAdd(&g_stats[COUT+4*t+2], Q.z); atomicAdd(&g_stats[COUT+4*t+3], Q.w);
        }
    }

    // ---------------- barrier 2 ------------------------------------------------
    __threadfence();
    __syncthreads();
    if (t == 0) {
        atomicAdd(&g_bar2, 1u);
        while (*(volatile unsigned*)&g_bar2 < (unsigned)NBLK) __nanosleep(64);
    }
    __syncthreads();
    __threadfence();

    // ---------------- phase 2b: finalize + normalize (L2-hot) -----------------
    if (t < COUT) {
        float inv_n = 1.0f / (float)NVOX;
        float mean  = g_stats[t] * inv_n;
        float var   = g_stats[COUT + t] * inv_n - mean*mean;
        float inv   = rsqrtf(var + 1e-5f);
        float scl   = gamma[t] * inv;
        sc[t] = scl;
        sh[t] = beta[t] - mean*scl;
    }
    __syncthreads();

    {
        const int total4 = NVOX*COUT/4;
        float4* o4 = (float4*)out;
        for (int i = blockIdx.x*256 + t; i < total4; i += NBLK*256) {
            float4 v = o4[i];
            int bd = (i*4) & (COUT-1);
            v.x = fmaxf(fmaf(v.x, sc[bd+0], sh[bd+0]), 0.f);
            v.y = fmaxf(fmaf(v.y, sc[bd+1], sh[bd+1]), 0.f);
            v.z = fmaxf(fmaf(v.z, sc[bd+2], sh[bd+2]), 0.f);
            v.w = fmaxf(fmaf(v.w, sc[bd+3], sh[bd+3]), 0.f);
            o4[i] = v;
        }
    }

    // ---------------- reset for next graph replay ------------------------------
    __syncthreads();
    if (t == 0) {
        unsigned d = atomicAdd(&g_done, 1u);
        if (d == (unsigned)NBLK - 1u) {
            #pragma unroll
            for (int i = 0; i < 2*COUT; i++) g_stats[i] = 0.f;
            __threadfence();
            g_work = 0u;
            g_bar1 = 0u;
            g_bar2 = 0u;
            g_done = 0u;
            __threadfence();
        }
    }
}

// ---------------------------------------------------------------- launch
extern "C" void kernel_launch(void* const* d_in, const int* in_sizes, int n_in,
                              void* d_out, int out_size)
{
    const float* features = (const float*)d_in[0];  // [150000,32]
    const float* weight   = (const float*)d_in[1];  // [27,32,64]
    const float* gamma    = (const float*)d_in[2];  // [64]
    const float* beta     = (const float*)d_in[3];  // [64]
    const int*   nbr      = (const int*)  d_in[4];  // [27,150000]
    float* out = (float*)d_out;                     // [150000,64]

    cudaFuncSetAttribute(fused_kernel,
                         cudaFuncAttributeMaxDynamicSharedMemorySize, SMEM_BYTES);
    fused_kernel<<<NBLK, 256, SMEM_BYTES>>>(features, weight, gamma, beta, nbr, out);
}